// round 3
// baseline (speedup 1.0000x reference)
#include <cuda_runtime.h>
#include <cuda_bf16.h>
#include <cstdint>
#include <math.h>

#define NPTS 8192
#define NMAT ((size_t)NPTS * (size_t)NPTS)
#define TS   512
#define NT   16
#define NPAIRS 136         /* NT*(NT+1)/2 */

#define EPSV     0.05f
#define INV_EPS  20.0f
#define CLOGN    0.45054567f   /* eps * log(8192) */

// ---- scratch (static device memory; allocation-free) ----
__device__ __nv_bfloat16 g_Kxy[NMAT];
__device__ __nv_bfloat16 g_Kyx[NMAT];
__device__ __nv_bfloat16 g_Kxx[NMAT];   // lower-triangle tiles only
__device__ __nv_bfloat16 g_Kyy[NMAT];   // lower-triangle tiles only

__device__ float g_P[2][2][NPTS][NT];   // [parity][xx|yy][row][coltile] partial sums
__device__ float g_hs[2][NPTS];         // row sums s of h_{t} (latest step), per chain
__device__ float g_hv[2][2][NPTS];      // final-values staging [chain][h99|h100][row]

__device__ float g_f[NPTS], g_g[NPTS], g_wf[NPTS], g_wg[NPTS];
__device__ float g_cham[NPTS];

__device__ __forceinline__ float bf_lo(unsigned u){ return __uint_as_float(u << 16); }
__device__ __forceinline__ float bf_hi(unsigned u){ return __uint_as_float(u & 0xffff0000u); }

__global__ void init_kernel(){
  int i = blockIdx.x * blockDim.x + threadIdx.x;
  if (i < NPTS){
    g_wf[i] = 1.f; g_wg[i] = 1.f;
    g_f[i] = 0.f;  g_g[i] = 0.f;
  }
  // P[0] := 512 so that sum16 = 8192 -> w = 1, h = 0
  int tot = 2 * NPTS * NT;
  for (int j = i; j < tot; j += gridDim.x * blockDim.x)
    (&g_P[0][0][0][0])[j] = 512.f;
}

// One block per row. K[row][:] = exp(-sqrt(d2+1e-12)/eps) in bf16.
// which: 0=Kxy  1=Kyx (+chamfer row mins)  2=Kxx (triangle)  3=Kyy (triangle)
__global__ void __launch_bounds__(256) fill_kernel(const float* __restrict__ Apts,
                                                   const float* __restrict__ Bpts,
                                                   int which){
  __nv_bfloat16* K; float* rowmin = nullptr;
  if      (which == 0)  K = g_Kxy;
  else if (which == 1){ K = g_Kyx; rowmin = g_cham; }
  else if (which == 2)  K = g_Kxx;
  else                  K = g_Kyy;

  int row = blockIdx.x;
  int climit = (which >= 2) ? (((row >> 9) + 1) << 9) : NPTS;
  float4 ap = reinterpret_cast<const float4*>(Apts)[row];
  float na = ap.x*ap.x + ap.y*ap.y + ap.z*ap.z;
  float mn = INFINITY;
  unsigned* Kout = reinterpret_cast<unsigned*>(K + ((size_t)row << 13));
  const float4* Bv = reinterpret_cast<const float4*>(Bpts);

  for (int k = threadIdx.x; k < climit/2; k += 256){
    float4 b0 = Bv[2*k], b1 = Bv[2*k + 1];
    float d0 = fmaxf(na + (b0.x*b0.x + b0.y*b0.y + b0.z*b0.z)
                        - 2.f*(ap.x*b0.x + ap.y*b0.y + ap.z*b0.z), 0.f);
    float d1 = fmaxf(na + (b1.x*b1.x + b1.y*b1.y + b1.z*b1.z)
                        - 2.f*(ap.x*b1.x + ap.y*b1.y + ap.z*b1.z), 0.f);
    mn = fminf(mn, fminf(d0, d1));
    float e0 = __expf(-INV_EPS * sqrtf(d0 + 1e-12f));
    float e1 = __expf(-INV_EPS * sqrtf(d1 + 1e-12f));
    __nv_bfloat162 p = __floats2bfloat162_rn(e0, e1);
    Kout[k] = *reinterpret_cast<unsigned*>(&p);
  }

  if (rowmin){
    __shared__ float sredm[8];
    int lane = threadIdx.x & 31, wid = threadIdx.x >> 5;
    #pragma unroll
    for (int o = 16; o; o >>= 1) mn = fminf(mn, __shfl_xor_sync(0xffffffffu, mn, o));
    if (lane == 0) sredm[wid] = mn;
    __syncthreads();
    if (threadIdx.x == 0){
      float m = sredm[0];
      #pragma unroll
      for (int w = 1; w < 8; w++) m = fminf(m, sredm[w]);
      rowmin[row] = m;
    }
  }
}

// Blocks 0..255: xy chain (full rows). Blocks 256..527: symmetric triangle tiles.
__global__ void __launch_bounds__(256) step_kernel(int t){
  __shared__ __align__(16) float sbuf[NPTS];
  int tid = threadIdx.x, lane = tid & 31, wid = tid >> 5;
  int b = blockIdx.x;
  bool even = (t & 1) == 0;

  if (b < 256){
    // ---------------- xy chain ----------------
    const __nv_bfloat16* K = even ? g_Kxy : g_Kyx;
    const float* win  = even ? g_wg : g_wf;
    float* vout = even ? g_f  : g_g;
    float* wout = even ? g_wf : g_wg;

    for (int i = tid; i < NPTS/4; i += 256)
      reinterpret_cast<float4*>(sbuf)[i] = reinterpret_cast<const float4*>(win)[i];
    __syncthreads();

    int base = b << 5;
    #pragma unroll
    for (int p = 0; p < 2; p++){
      int row0 = base + (wid << 2) + (p << 1);
      const uint4* K0 = reinterpret_cast<const uint4*>(K + ((size_t)row0 << 13));
      const uint4* K1 = reinterpret_cast<const uint4*>(K + ((size_t)(row0 + 1) << 13));
      float s0 = 0.f, s1 = 0.f;
      #pragma unroll 4
      for (int it = lane; it < NPTS/8; it += 32){
        uint4 a = K0[it];
        uint4 c = K1[it];
        const float4* vp = reinterpret_cast<const float4*>(sbuf + (it << 3));
        float4 v0 = vp[0], v1 = vp[1];
        s0 += bf_lo(a.x)*v0.x + bf_hi(a.x)*v0.y + bf_lo(a.y)*v0.z + bf_hi(a.y)*v0.w
            + bf_lo(a.z)*v1.x + bf_hi(a.z)*v1.y + bf_lo(a.w)*v1.z + bf_hi(a.w)*v1.w;
        s1 += bf_lo(c.x)*v0.x + bf_hi(c.x)*v0.y + bf_lo(c.y)*v0.z + bf_hi(c.y)*v0.w
            + bf_lo(c.z)*v1.x + bf_hi(c.z)*v1.y + bf_lo(c.w)*v1.z + bf_hi(c.w)*v1.w;
      }
      #pragma unroll
      for (int o = 16; o; o >>= 1){
        s0 += __shfl_xor_sync(0xffffffffu, s0, o);
        s1 += __shfl_xor_sync(0xffffffffu, s1, o);
      }
      if (lane == 0){
        s0 = fmaxf(s0, 1e-35f); s1 = fmaxf(s1, 1e-35f);
        vout[row0]     = CLOGN - EPSV * __logf(s0);
        vout[row0 + 1] = CLOGN - EPSV * __logf(s1);
        wout[row0]     = 8192.f / s0;
        wout[row0 + 1] = 8192.f / s1;
      }
    }
  } else {
    // ------------- symmetric chains: lower-triangle tiles -------------
    int sb  = b - 256;
    int mat = (sb >= NPAIRS) ? 1 : 0;
    int p   = mat ? sb - NPAIRS : sb;
    int A = (int)((sqrtf(8.f * p + 1.f) - 1.f) * 0.5f);
    while ((A + 1) * (A + 2) / 2 <= p) A++;
    while (A * (A + 1) / 2 > p) A--;
    int B = p - ((A * (A + 1)) >> 1);
    bool diag = (A == B);

    const __nv_bfloat16* K = mat ? g_Kyy : g_Kxx;
    const float (*Pin)[NT] = g_P[t & 1][mat];
    float (*Pout)[NT]      = g_P[(t + 1) & 1][mat];

    float* wcol = sbuf;            // 512
    float* wrow = sbuf + TS;       // 512
    float* cs   = sbuf + 2 * TS;   // 8 * 512 staging

    // Recompute w^{(t)} slices from partials (L2-resident, 1MB total).
    for (int i = tid; i < TS; i += 256){
      int rB = B * TS + i, rA = A * TS + i;
      const float4* pb = reinterpret_cast<const float4*>(Pin[rB]);
      float4 q0 = pb[0], q1 = pb[1], q2 = pb[2], q3 = pb[3];
      float sB = (q0.x+q0.y+q0.z+q0.w) + (q1.x+q1.y+q1.z+q1.w)
               + (q2.x+q2.y+q2.z+q2.w) + (q3.x+q3.y+q3.z+q3.w);
      sB = fmaxf(sB, 1e-35f);
      wcol[i] = 8192.f / sB;
      const float4* pa = reinterpret_cast<const float4*>(Pin[rA]);
      float4 r0 = pa[0], r1 = pa[1], r2 = pa[2], r3 = pa[3];
      float sA = (r0.x+r0.y+r0.z+r0.w) + (r1.x+r1.y+r1.z+r1.w)
               + (r2.x+r2.y+r2.z+r2.w) + (r3.x+r3.y+r3.z+r3.w);
      sA = fmaxf(sA, 1e-35f);
      wrow[i] = 8192.f / sA;
      if (B == 0) g_hs[mat][rA] = sA;   // persist s of h_t (covers all rows once)
    }
    __syncthreads();

    float4 acc[4];
    #pragma unroll
    for (int i = 0; i < 4; i++) acc[i] = make_float4(0.f, 0.f, 0.f, 0.f);

    // 2 rows per warp-iteration: interleaved reductions, 4 LDGs in flight
    for (int r0 = (wid << 1); r0 < TS; r0 += 16){
      const uint4* Kr0 = reinterpret_cast<const uint4*>(
          K + (((size_t)(A * TS + r0)) << 13) + (size_t)B * TS);
      const uint4* Kr1 = reinterpret_cast<const uint4*>(
          K + (((size_t)(A * TS + r0 + 1)) << 13) + (size_t)B * TS);
      float wr0 = wrow[r0], wr1 = wrow[r0 + 1];
      float rd0 = 0.f, rd1 = 0.f;
      #pragma unroll
      for (int i = 0; i < 2; i++){
        uint4 ka = Kr0[(i << 5) + lane];
        uint4 kb = Kr1[(i << 5) + lane];
        const float4* wp = reinterpret_cast<const float4*>(wcol + (i << 8) + (lane << 3));
        float4 w0 = wp[0], w1 = wp[1];
        float a0 = bf_lo(ka.x), a1 = bf_hi(ka.x), a2 = bf_lo(ka.y), a3 = bf_hi(ka.y);
        float a4 = bf_lo(ka.z), a5 = bf_hi(ka.z), a6 = bf_lo(ka.w), a7 = bf_hi(ka.w);
        float b0 = bf_lo(kb.x), b1 = bf_hi(kb.x), b2 = bf_lo(kb.y), b3 = bf_hi(kb.y);
        float b4 = bf_lo(kb.z), b5 = bf_hi(kb.z), b6 = bf_lo(kb.w), b7 = bf_hi(kb.w);
        rd0 += a0*w0.x + a1*w0.y + a2*w0.z + a3*w0.w
             + a4*w1.x + a5*w1.y + a6*w1.z + a7*w1.w;
        rd1 += b0*w0.x + b1*w0.y + b2*w0.z + b3*w0.w
             + b4*w1.x + b5*w1.y + b6*w1.z + b7*w1.w;
        if (!diag){
          acc[2*i].x   += a0*wr0 + b0*wr1;  acc[2*i].y   += a1*wr0 + b1*wr1;
          acc[2*i].z   += a2*wr0 + b2*wr1;  acc[2*i].w   += a3*wr0 + b3*wr1;
          acc[2*i+1].x += a4*wr0 + b4*wr1;  acc[2*i+1].y += a5*wr0 + b5*wr1;
          acc[2*i+1].z += a6*wr0 + b6*wr1;  acc[2*i+1].w += a7*wr0 + b7*wr1;
        }
      }
      #pragma unroll
      for (int o = 16; o; o >>= 1){
        rd0 += __shfl_xor_sync(0xffffffffu, rd0, o);
        rd1 += __shfl_xor_sync(0xffffffffu, rd1, o);
      }
      if (lane == 0){
        Pout[A * TS + r0][B]     = rd0;
        Pout[A * TS + r0 + 1][B] = rd1;
      }
    }

    if (!diag){
      #pragma unroll
      for (int i = 0; i < 2; i++){
        *reinterpret_cast<float4*>(cs + wid * TS + (i << 8) + (lane << 3))     = acc[2*i];
        *reinterpret_cast<float4*>(cs + wid * TS + (i << 8) + (lane << 3) + 4) = acc[2*i+1];
      }
      __syncthreads();
      for (int c = tid; c < TS; c += 256){
        float s = 0.f;
        #pragma unroll
        for (int w = 0; w < 8; w++) s += cs[w * TS + c];
        Pout[B * TS + c][A] = s;
      }
    }
  }
}

// Convert last partials into h99/h100 values. parity: P parity holding h_100.
__global__ void __launch_bounds__(256) finish2_kernel(int parity){
  int idx = blockIdx.x * 256 + threadIdx.x;   // 0..16383
  int mat = idx >> 13;
  int r   = idx & (NPTS - 1);
  const float4* Pp = reinterpret_cast<const float4*>(g_P[parity][mat][r]);
  float4 p0 = Pp[0], p1 = Pp[1], p2 = Pp[2], p3 = Pp[3];
  float s100 = (p0.x+p0.y+p0.z+p0.w) + (p1.x+p1.y+p1.z+p1.w)
             + (p2.x+p2.y+p2.z+p2.w) + (p3.x+p3.y+p3.z+p3.w);
  s100 = fmaxf(s100, 1e-35f);
  float s99 = fmaxf(g_hs[mat][r], 1e-35f);
  g_hv[mat][0][r] = CLOGN - EPSV * __logf(s99);
  g_hv[mat][1][r] = CLOGN - EPSV * __logf(s100);
}

__global__ void final_kernel(float* out){
  __shared__ float sred[8];
  int tid = threadIdx.x, lane = tid & 31, wid = tid >> 5;
  const float* arrs[7] = { g_f, g_g, g_hv[0][0], g_hv[0][1], g_hv[1][0], g_hv[1][1], g_cham };
  float totals[7];
  for (int a = 0; a < 7; a++){
    float s = 0.f;
    for (int i = tid; i < NPTS; i += 256) s += arrs[a][i];
    #pragma unroll
    for (int o = 16; o; o >>= 1) s += __shfl_xor_sync(0xffffffffu, s, o);
    __syncthreads();
    if (lane == 0) sred[wid] = s;
    __syncthreads();
    if (tid == 0){
      float tt = 0.f;
      #pragma unroll
      for (int w = 0; w < 8; w++) tt += sred[w];
      totals[a] = tt;
    }
  }
  if (tid == 0){
    const float invN = 1.f / (float)NPTS;
    float ot_xy = (totals[0] + totals[1]) * invN;
    float ot_xx = (totals[2] + totals[3]) * invN;
    float ot_yy = (totals[4] + totals[5]) * invN;
    float cham  = totals[6] * invN;
    float emd = ot_xy - 0.5f * ot_xx - 0.5f * ot_yy;
    out[0] = 0.2f * cham + 0.8f * emd;
  }
}

extern "C" void kernel_launch(void* const* d_in, const int* in_sizes, int n_in,
                              void* d_out, int out_size){
  const float* pred = (const float*)d_in[0];
  const float* gt   = (const float*)d_in[1];
  float* out = (float*)d_out;

  init_kernel<<<256, 256>>>();
  fill_kernel<<<NPTS, 256>>>(pred, gt,   0);   // Kxy
  fill_kernel<<<NPTS, 256>>>(gt,   pred, 1);   // Kyx + chamfer row mins
  fill_kernel<<<NPTS, 256>>>(pred, pred, 2);   // Kxx (lower triangle)
  fill_kernel<<<NPTS, 256>>>(gt,   gt,   3);   // Kyy (lower triangle)

  for (int t = 0; t < 100; t++)
    step_kernel<<<256 + 2 * NPAIRS, 256>>>(t);

  finish2_kernel<<<64, 256>>>(100 & 1);        // parity 0 holds h_100 partials
  final_kernel<<<1, 256>>>(out);
}